// round 4
// baseline (speedup 1.0000x reference)
#include <cuda_runtime.h>
#include <cuda_bf16.h>
#include <cstdint>

#define D_FEAT      64
#define ROW_BYTES   256           // D_FEAT * 4
#define N_NODES_MAX 100000
#define EPS         64            // edges per 16-thread group
#define SUBS        8             // groups per block
#define EPB         (EPS * SUBS)  // 512 edges per block
#define THREADS     128
#define MAX_GROUPS  40960         // supports up to ~2.6M edges

// Scratch (allocation-free per harness rules).
__device__ float g_tmp[(size_t)N_NODES_MAX * D_FEAT];
__device__ float g_carry[(size_t)MAX_GROUPS * D_FEAT];
__device__ int   g_carry_row[MAX_GROUPS];

__device__ __forceinline__ void red_add_v4(float* p, float4 a) {
    asm volatile("red.global.add.v4.f32 [%0], {%1, %2, %3, %4};"
                 :: "l"(p), "f"(a.x), "f"(a.y), "f"(a.z), "f"(a.w)
                 : "memory");
}

// Sorted-row SpMM with carry-based segmented reduction (NO pre-zeroed dst).
// Each 16-thread group walks EPS consecutive edges.
//  - Runs STARTING inside the group -> exclusive, flushed with STG.128.
//  - Leading run CONTINUING from the previous group -> partial written to
//    per-group carry slot (plain STG); fixup kernel red.adds it later.
//  - Gap rows (no edges anywhere, proven by sorted adjacency) -> STG zeros.
__global__ void __launch_bounds__(THREADS)
spmm_kernel(const float* __restrict__ src,
            const int*   __restrict__ erow,
            const int*   __restrict__ ecol,
            const float* __restrict__ eval,
            float*       __restrict__ dst,
            float*       __restrict__ carry,
            int*         __restrict__ carry_row,
            int n_edges, int n_rows) {
    __shared__ alignas(16) int   s_row[EPB];
    __shared__ alignas(16) int   s_off[EPB];   // col * ROW_BYTES
    __shared__ alignas(16) float s_val[EPB];

    const int base = blockIdx.x * EPB;
    const int tid  = threadIdx.x;

    // Vectorized staging; pad with last valid row, val = 0 (harmless).
    {
        const int i = tid * 4;
        const int e = base + i;
        if (e + 3 < n_edges) {
            int4   r = *reinterpret_cast<const int4*>(erow + e);
            int4   c = *reinterpret_cast<const int4*>(ecol + e);
            float4 v = *reinterpret_cast<const float4*>(eval + e);
            c.x *= ROW_BYTES; c.y *= ROW_BYTES; c.z *= ROW_BYTES; c.w *= ROW_BYTES;
            *reinterpret_cast<int4*>(s_row + i)   = r;
            *reinterpret_cast<int4*>(s_off + i)   = c;
            *reinterpret_cast<float4*>(s_val + i) = v;
        } else {
            #pragma unroll
            for (int k = 0; k < 4; k++) {
                int ee   = e + k;
                int esrc = min(ee, n_edges - 1);
                int in   = (ee < n_edges);
                s_row[i + k] = erow[esrc];
                s_off[i + k] = in ? ecol[esrc] * ROW_BYTES : 0;
                s_val[i + k] = in ? eval[esrc] : 0.f;
            }
        }
    }
    __syncthreads();

    const int d4   = tid & 15;
    const int sub  = tid >> 4;
    const int off  = sub * EPS;
    const int gid  = blockIdx.x * SUBS + sub;
    const int goff = base + off;                 // global index of group's first edge
    const char* sp = reinterpret_cast<const char*>(src + d4 * 4);
    const float4 z4 = make_float4(0.f, 0.f, 0.f, 0.f);

    if (goff >= n_edges) {                       // fully-padded group
        if (d4 == 0) carry_row[gid] = -1;
        return;
    }

    const int first = s_row[off];
    const int prev  = (off > 0) ? s_row[off - 1]
                                : ((goff == 0) ? -1 : erow[goff - 1]);
    const bool continuation = (prev == first);
    if (d4 == 0) carry_row[gid] = continuation ? first : -1;

    // Leading gap: rows (prev, first) have no edges anywhere -> zeros.
    for (int rr = prev + 1; rr < first; rr++)
        *reinterpret_cast<float4*>(dst + (size_t)rr * D_FEAT + d4 * 4) = z4;

    int    cur       = first;
    bool   first_run = true;
    float4 acc       = make_float4(0.f, 0.f, 0.f, 0.f);

    for (int ib = 0; ib < EPS; ib += 8) {
        const int4   ra = *reinterpret_cast<const int4*>(s_row + off + ib);
        const int4   rb = *reinterpret_cast<const int4*>(s_row + off + ib + 4);
        const int4   ca = *reinterpret_cast<const int4*>(s_off + off + ib);
        const int4   cb = *reinterpret_cast<const int4*>(s_off + off + ib + 4);
        const float4 va = *reinterpret_cast<const float4*>(s_val + off + ib);
        const float4 vb = *reinterpret_cast<const float4*>(s_val + off + ib + 4);

        // 8 gathers in flight (MLP = 8)
        const float4 g0 = *reinterpret_cast<const float4*>(sp + ca.x);
        const float4 g1 = *reinterpret_cast<const float4*>(sp + ca.y);
        const float4 g2 = *reinterpret_cast<const float4*>(sp + ca.z);
        const float4 g3 = *reinterpret_cast<const float4*>(sp + ca.w);
        const float4 g4 = *reinterpret_cast<const float4*>(sp + cb.x);
        const float4 g5 = *reinterpret_cast<const float4*>(sp + cb.y);
        const float4 g6 = *reinterpret_cast<const float4*>(sp + cb.z);
        const float4 g7 = *reinterpret_cast<const float4*>(sp + cb.w);

        #define STEP(R, V, G)                                                \
        do {                                                                 \
            if ((R) != cur) {                                                \
                if (first_run && continuation) {                             \
                    *reinterpret_cast<float4*>(                              \
                        carry + (size_t)gid * D_FEAT + d4 * 4) = acc;        \
                } else {                                                     \
                    *reinterpret_cast<float4*>(                              \
                        dst + (size_t)cur * D_FEAT + d4 * 4) = acc;          \
                }                                                            \
                first_run = false;                                           \
                for (int rr = cur + 1; rr < (R); rr++)                       \
                    *reinterpret_cast<float4*>(                              \
                        dst + (size_t)rr * D_FEAT + d4 * 4) = z4;            \
                acc = make_float4(0.f, 0.f, 0.f, 0.f);                       \
                cur = (R);                                                   \
            }                                                                \
            acc.x += (V) * (G).x;                                            \
            acc.y += (V) * (G).y;                                            \
            acc.z += (V) * (G).z;                                            \
            acc.w += (V) * (G).w;                                            \
        } while (0)

        STEP(ra.x, va.x, g0);
        STEP(ra.y, va.y, g1);
        STEP(ra.z, va.z, g2);
        STEP(ra.w, va.w, g3);
        STEP(rb.x, vb.x, g4);
        STEP(rb.y, vb.y, g5);
        STEP(rb.z, vb.z, g6);
        STEP(rb.w, vb.w, g7);
        #undef STEP
    }

    // Final flush: leading-continuation run -> carry slot; else base STG.
    if (first_run && continuation) {
        *reinterpret_cast<float4*>(carry + (size_t)gid * D_FEAT + d4 * 4) = acc;
    } else {
        *reinterpret_cast<float4*>(dst + (size_t)cur * D_FEAT + d4 * 4) = acc;
    }

    // Group containing the global last edge zeroes all trailing rows.
    if (goff <= n_edges - 1 && n_edges - 1 < goff + EPS) {
        for (int rr = cur + 1; rr < n_rows; rr++)
            *reinterpret_cast<float4*>(dst + (size_t)rr * D_FEAT + d4 * 4) = z4;
    }
}

// Add per-group leading-run carries into the STG'd base values.
__global__ void fixup_kernel(float* __restrict__ dst,
                             const float* __restrict__ carry,
                             const int*   __restrict__ carry_row,
                             int n_groups) {
    int t  = blockIdx.x * blockDim.x + threadIdx.x;
    int g  = t >> 4;
    int d4 = t & 15;
    if (g >= n_groups) return;
    int r = carry_row[g];
    if (r < 0) return;
    float4 c = *reinterpret_cast<const float4*>(carry + (size_t)g * D_FEAT + d4 * 4);
    red_add_v4(dst + (size_t)r * D_FEAT + d4 * 4, c);
}

extern "C" void kernel_launch(void* const* d_in, const int* in_sizes, int n_in,
                              void* d_out, int out_size) {
    const float* x    = (const float*)d_in[0];
    const int*   erow = (const int*)  d_in[1];
    const int*   ecol = (const int*)  d_in[2];
    const float* eval = (const float*)d_in[3];
    float*       out  = (float*)d_out;

    const int n_edges = in_sizes[1];
    const int n_rows  = out_size / D_FEAT;

    void *tmp_sym = nullptr, *cv_sym = nullptr, *cr_sym = nullptr;
    cudaGetSymbolAddress(&tmp_sym, g_tmp);
    cudaGetSymbolAddress(&cv_sym,  g_carry);
    cudaGetSymbolAddress(&cr_sym,  g_carry_row);
    float* tmp   = (float*)tmp_sym;
    float* cval  = (float*)cv_sym;
    int*   crow  = (int*)cr_sym;

    const int sgrid    = (n_edges + EPB - 1) / EPB;
    const int n_groups = sgrid * SUBS;
    const int fgrid    = (n_groups * 16 + THREADS - 1) / THREADS;

    // Hop 1: tmp = A @ x
    spmm_kernel<<<sgrid, THREADS>>>(x, erow, ecol, eval, tmp, cval, crow,
                                    n_edges, n_rows);
    fixup_kernel<<<fgrid, THREADS>>>(tmp, cval, crow, n_groups);

    // Hop 2: out = A @ tmp
    spmm_kernel<<<sgrid, THREADS>>>(tmp, erow, ecol, eval, out, cval, crow,
                                    n_edges, n_rows);
    fixup_kernel<<<fgrid, THREADS>>>(out, cval, crow, n_groups);
}